// round 16
// baseline (speedup 1.0000x reference)
#include <cuda_runtime.h>
#include <cuda_fp16.h>
#include <cstdint>

#define E_TOT  43234
#define ET     4
#define NWTILE 10809           // ceil(E_TOT/4)
#define NBLK   444             // 3 CTA/SM * 148
#define NTHR   256

// fp16 rotated+NEGATED head: g_head16[(q*32+b)*8 + j] = -re(4q+j), +4+j = -im(4q+j)
__device__ __half g_head16[64 * 32 * 8];   // 32 KB
__device__ int g_ctr;

// ---------- f32x2 packed helpers (sm_103a) ----------
static __device__ __forceinline__ unsigned long long addx2(unsigned long long a, unsigned long long b) {
    unsigned long long r; asm("add.rn.f32x2 %0, %1, %2;" : "=l"(r) : "l"(a), "l"(b)); return r;
}
static __device__ __forceinline__ unsigned long long mulx2(unsigned long long a, unsigned long long b) {
    unsigned long long r; asm("mul.rn.f32x2 %0, %1, %2;" : "=l"(r) : "l"(a), "l"(b)); return r;
}
static __device__ __forceinline__ unsigned long long fmax2(unsigned long long a, unsigned long long b, unsigned long long c) {
    unsigned long long r; asm("fma.rn.f32x2 %0, %1, %2, %3;" : "=l"(r) : "l"(a), "l"(b), "l"(c)); return r;
}
static __device__ __forceinline__ void unpack2(unsigned long long v, float& lo, float& hi) {
    asm("mov.b64 {%0, %1}, %2;" : "=f"(lo), "=f"(hi) : "l"(v));
}
static __device__ __forceinline__ unsigned long long packf2(float2 f) {
    unsigned long long r; asm("mov.b64 %0, {%1, %2};" : "=l"(r) : "f"(f.x), "f"(f.y)); return r;
}
static __device__ __forceinline__ float sqrt_approx(float x) {
    float r; asm("sqrt.approx.f32 %0, %1;" : "=f"(r) : "f"(x)); return r;
}

// ---------- prep: rotate head, negate, quantize fp16; reset steal counter ----------
__global__ void prep_kernel(const float* __restrict__ head, const float* __restrict__ rel) {
    int b = blockIdx.x, d = threadIdx.x;
    if (b == 0 && d == 0) g_ctr = 0;
    float re_h = head[b * 512 + d];
    float im_h = head[b * 512 + 256 + d];
    float phase = rel[b * 256 + d] * 100.53096491487338f;  // rel * 32*pi
    float s, c; sincosf(phase, &s, &c);
    float re_rot = re_h * c - im_h * s;
    float im_rot = re_h * s + im_h * c;
    int q = d >> 2, j = d & 3;
    g_head16[((q * 32) + b) * 8 + j]     = __float2half(-re_rot);
    g_head16[((q * 32) + b) * 8 + 4 + j] = __float2half(-im_rot);
}

// ---------- main: lane = b, warp = 4-entity tile; staged entities (LDG+STS -> bcast LDS),
//            fp16 head (1 LDS.128/q), per-warp double buffer, 3 CTA/SM ----------
__global__ void __launch_bounds__(NTHR, 3)
dist_kernel(const float* __restrict__ ent, float* __restrict__ out) {
    extern __shared__ char smem[];
    // [0, 32768): 8 warps * (2 bufs * 2KB) entity stages
    // [32768, 65536): fp16 head table (32 KB)
    uint4* Hs = reinterpret_cast<uint4*>(smem + 32768);
    {
        const uint4* src = reinterpret_cast<const uint4*>(g_head16);
        for (int i = threadIdx.x; i < 2048; i += NTHR) Hs[i] = src[i];
    }
    __syncthreads();

    const int lane = threadIdx.x & 31;
    const int wid  = threadIdx.x >> 5;
    char* wstage = smem + wid * 4096;                         // 2 bufs * 2KB
    const int foff = (lane >> 4) * 1024 + (lane & 15) * 16;   // gmem fill offset per lane
    const int soff = (lane >> 4) * 256 + (lane & 15) * 16;    // smem fill offset per lane
    const uint4* __restrict__ hs = Hs + lane;                 // hs[q*32]

    int tile;
    if (lane == 0) tile = atomicAdd(&g_ctr, 1);
    tile = __shfl_sync(0xffffffffu, tile, 0);
    if (tile >= NWTILE) return;

    int e0 = tile * ET;
    if (e0 > E_TOT - ET) e0 = E_TOT - ET;
    const char* base = reinterpret_cast<const char*>(ent) + (size_t)e0 * 2048;

    // fill chunk 0 into buf 0: 4 coalesced LDG.128 + 4 STS.128
    uint4 g0, g1, g2, g3;
    {
        const char* a = base + foff;
        g0 = *reinterpret_cast<const uint4*>(a);
        g1 = *reinterpret_cast<const uint4*>(a + 2048);
        g2 = *reinterpret_cast<const uint4*>(a + 4096);
        g3 = *reinterpret_cast<const uint4*>(a + 6144);
        char* s = wstage + soff;
        *reinterpret_cast<uint4*>(s)        = g0;
        *reinterpret_cast<uint4*>(s + 512)  = g1;
        *reinterpret_cast<uint4*>(s + 1024) = g2;
        *reinterpret_cast<uint4*>(s + 1536) = g3;
    }
    __syncwarp();

    int cur = 0;
    while (true) {
        // grab next tile now (cross-tile chunk-0 prefetch needs its address)
        int ntile;
        if (lane == 0) ntile = atomicAdd(&g_ctr, 1);
        ntile = __shfl_sync(0xffffffffu, ntile, 0);
        int ne0 = (ntile < NWTILE) ? ntile * ET : 0;
        if (ne0 > E_TOT - ET) ne0 = E_TOT - ET;
        const char* nbase = reinterpret_cast<const char*>(ent) + (size_t)ne0 * 2048;

        float acc0[ET] = {0, 0, 0, 0}, acc1[ET] = {0, 0, 0, 0};

#pragma unroll
        for (int c = 0; c < 4; c++) {
            // issue fill LDGs for next chunk (or next tile's chunk 0)
            const char* a = ((c < 3) ? (base + (c + 1) * 256) : nbase) + foff;
            g0 = *reinterpret_cast<const uint4*>(a);
            g1 = *reinterpret_cast<const uint4*>(a + 2048);
            g2 = *reinterpret_cast<const uint4*>(a + 4096);
            g3 = *reinterpret_cast<const uint4*>(a + 6144);

            // consume chunk c: per q: 8 bcast LDS + 1 fp16 head LDS
            const char* sb = wstage + cur * 2048;
#pragma unroll 4
            for (int qq = 0; qq < 16; qq++) {
                const int q = c * 16 + qq;
                ulonglong2 er[ET], ei[ET];
#pragma unroll
                for (int t = 0; t < ET; t++) {
                    er[t] = *reinterpret_cast<const ulonglong2*>(sb + t * 512 + qq * 16);
                    ei[t] = *reinterpret_cast<const ulonglong2*>(sb + t * 512 + 256 + qq * 16);
                }
                // fp16 head quad -> 4 f32x2 operands
                uint4 hh = hs[q * 32];
                const __half2* hp = reinterpret_cast<const __half2*>(&hh);
                unsigned long long h0x = packf2(__half22float2(hp[0]));  // -re {4q,4q+1}
                unsigned long long h1x = packf2(__half22float2(hp[1]));  // -re {4q+2,4q+3}
                unsigned long long h0y = packf2(__half22float2(hp[2]));  // -im {4q,4q+1}
                unsigned long long h1y = packf2(__half22float2(hp[3]));  // -im {4q+2,4q+3}
#pragma unroll
                for (int t = 0; t < ET; t++) {
                    unsigned long long a0 = addx2(er[t].x, h0x);
                    unsigned long long b0 = addx2(ei[t].x, h0y);
                    unsigned long long a1 = addx2(er[t].y, h1x);
                    unsigned long long b1 = addx2(ei[t].y, h1y);
                    unsigned long long p0 = fmax2(b0, b0, mulx2(a0, a0));
                    unsigned long long p1 = fmax2(b1, b1, mulx2(a1, a1));
                    float x0, x1, y0, y1;
                    unpack2(p0, x0, x1);
                    unpack2(p1, y0, y1);
                    acc0[t] += sqrt_approx(x0) + sqrt_approx(y0);
                    acc1[t] += sqrt_approx(x1) + sqrt_approx(y1);
                }
            }

            // store fills into the other buffer
            char* s = wstage + (cur ^ 1) * 2048 + soff;
            *reinterpret_cast<uint4*>(s)        = g0;
            *reinterpret_cast<uint4*>(s + 512)  = g1;
            *reinterpret_cast<uint4*>(s + 1024) = g2;
            *reinterpret_cast<uint4*>(s + 1536) = g3;
            __syncwarp();
            cur ^= 1;
        }

        float2* op = reinterpret_cast<float2*>(out + (size_t)lane * E_TOT + e0);
        op[0] = make_float2(6.0f - (acc0[0] + acc1[0]), 6.0f - (acc0[1] + acc1[1]));
        op[1] = make_float2(6.0f - (acc0[2] + acc1[2]), 6.0f - (acc0[3] + acc1[3]));

        if (ntile >= NWTILE) break;
        base = nbase;
        e0 = ne0;
    }
}

extern "C" void kernel_launch(void* const* d_in, const int* in_sizes, int n_in,
                              void* d_out, int out_size) {
    const float* head = (const float*)d_in[0];   // (32, 512)
    const float* rel  = (const float*)d_in[1];   // (32, 256)
    const float* ent  = (const float*)d_in[2];   // (43234, 512)
    float* out = (float*)d_out;                  // (32, 43234)

    cudaFuncSetAttribute(dist_kernel, cudaFuncAttributeMaxDynamicSharedMemorySize, 65536);

    prep_kernel<<<32, 256>>>(head, rel);
    dist_kernel<<<NBLK, NTHR, 65536>>>(ent, out);
}